// round 1
// baseline (speedup 1.0000x reference)
#include <cuda_runtime.h>
#include <cstddef>

// Problem constants (fixed by the dataset)
#define NB 2
#define NP 4096
#define NA 96
#define NF 32
#define NE 20

// Scratch for precomputed linear terms (graph-capturable: static device arrays)
__device__ float g_tgt[NB * NP * NF];   // scalar_reciever @ Wt + b1n
__device__ float g_src[NB * NA * NF];   // scalar @ Ws

// shifted softplus: log(1+e^x) - log(2), numerically stable
__device__ __forceinline__ float sspf(float x) {
    float t = __logf(1.0f + __expf(-fabsf(x)));
    return fmaxf(x, 0.0f) + t - 0.69314718055994531f;
}

// ---------------------------------------------------------------------------
// Precompute kernel: one warp per output row, lane = f.
// rows [0, NB*NP)            -> g_tgt   (uses W1n rows [F, 2F), + b1n folded)
// rows [NB*NP, NB*NP+NB*NA)  -> g_src   (uses W1n rows [0, F))
// ---------------------------------------------------------------------------
__global__ void precompute_kernel(const float* __restrict__ scalar,
                                  const float* __restrict__ srecv,
                                  const float* __restrict__ W1n,
                                  const float* __restrict__ b1n)
{
    int gw   = (blockIdx.x * blockDim.x + threadIdx.x) >> 5;
    int lane = threadIdx.x & 31;

    if (gw < NB * NP) {
        float xv  = srecv[gw * NF + lane];
        float acc = b1n[lane];
        #pragma unroll
        for (int k = 0; k < NF; k++) {
            float xk = __shfl_sync(0xffffffffu, xv, k);
            acc = fmaf(xk, W1n[(NF + k) * NF + lane], acc);
        }
        g_tgt[gw * NF + lane] = acc;
    } else if (gw < NB * NP + NB * NA) {
        int r = gw - NB * NP;
        float xv  = scalar[r * NF + lane];
        float acc = 0.0f;
        #pragma unroll
        for (int k = 0; k < NF; k++) {
            float xk = __shfl_sync(0xffffffffu, xv, k);
            acc = fmaf(xk, W1n[k * NF + lane], acc);
        }
        g_src[r * NF + lane] = acc;
    }
}

// ---------------------------------------------------------------------------
// Main kernel: block = one (b,p), thread = one a (96 threads).
// Each thread runs the full gates/nodes pipeline for its a with the f-vector
// in registers; weights are read as uniform (broadcast) LDS.128 loads.
// Per-a contributions are reduced over a via a padded shared buffer.
// ---------------------------------------------------------------------------
__global__ __launch_bounds__(96) void main_kernel(
    const float* __restrict__ expansion,   // (B,P,A,E)
    const float* __restrict__ mask,        // (B,P,A,1)
    const float* __restrict__ edge,        // (B,P,A,1)
    const float* __restrict__ W1e,         // (E,F)
    const float* __restrict__ b1e,         // (F)
    const float* __restrict__ W2e,         // (F,F)
    const float* __restrict__ b2e,         // (F)
    const float* __restrict__ W2n,         // (F,F)
    const float* __restrict__ b2n,         // (F)
    float* __restrict__ out)               // (B,P,1,F)
{
    __shared__ float sW1e[NE * NF];
    __shared__ float sW2e[NF * NF];
    __shared__ float sW2n[NF * NF];
    __shared__ float sb2e[NF];
    __shared__ float sb2n[NF];
    __shared__ float sb1e[NF];
    __shared__ float stgt[NF];
    __shared__ float sred[NA * 33];   // padded: stride 33 avoids bank conflicts

    const int bp = blockIdx.x;       // b*NP + p
    const int a  = threadIdx.x;      // 0..95
    const int b  = bp >> 12;         // NP == 4096

    // Cooperative weight staging
    for (int i = a; i < NE * NF; i += 96) sW1e[i] = W1e[i];
    for (int i = a; i < NF * NF; i += 96) { sW2e[i] = W2e[i]; sW2n[i] = W2n[i]; }
    if (a < NF) {
        sb2e[a] = b2e[a];
        sb2n[a] = b2n[a];
        sb1e[a] = b1e[a];
        stgt[a] = g_tgt[(size_t)bp * NF + a];   // one row per block
    }
    __syncthreads();

    // --- per-thread edge data ---
    float x[NE];
    {
        const float4* xr = reinterpret_cast<const float4*>(
            expansion + ((size_t)bp * NA + a) * NE);   // 80B rows: 16B-aligned
        #pragma unroll
        for (int i = 0; i < NE / 4; i++) {
            float4 v = xr[i];
            x[4 * i + 0] = v.x; x[4 * i + 1] = v.y;
            x[4 * i + 2] = v.z; x[4 * i + 3] = v.w;
        }
    }
    float m = mask[(size_t)bp * NA + a];
    float d = edge[(size_t)bp * NA + a];
    // mask * (1 - sigmoid(5*(d-3.5))) = mask / (1 + exp(5*(d-3.5)))
    float gm = m / (1.0f + __expf(5.0f * (d - 3.5f)));

    // --- gates path: ssp(x @ W1e + b1e) @ W2e + b2e ---
    float e1[NF];
    #pragma unroll
    for (int f = 0; f < NF; f++) e1[f] = sb1e[f];
    #pragma unroll
    for (int e = 0; e < NE; e++) {
        float xe = x[e];
        #pragma unroll
        for (int f = 0; f < NF; f++)
            e1[f] = fmaf(xe, sW1e[e * NF + f], e1[f]);
    }
    #pragma unroll
    for (int f = 0; f < NF; f++) e1[f] = sspf(e1[f]);

    float gate[NF];
    #pragma unroll
    for (int f = 0; f < NF; f++) gate[f] = sb2e[f];
    #pragma unroll
    for (int k = 0; k < NF; k++) {
        float s = e1[k];
        #pragma unroll
        for (int f = 0; f < NF; f++)
            gate[f] = fmaf(s, sW2e[k * NF + f], gate[f]);
    }

    // --- nodes path: ssp(src[a] + tgt[p] + b1n) @ W2n + b2n ---
    const float4* srow = reinterpret_cast<const float4*>(
        g_src + ((size_t)b * NA + a) * NF);
    #pragma unroll
    for (int q = 0; q < NF / 4; q++) {
        float4 v = srow[q];
        e1[4 * q + 0] = sspf(v.x + stgt[4 * q + 0]);
        e1[4 * q + 1] = sspf(v.y + stgt[4 * q + 1]);
        e1[4 * q + 2] = sspf(v.z + stgt[4 * q + 2]);
        e1[4 * q + 3] = sspf(v.w + stgt[4 * q + 3]);
    }

    float node[NF];
    #pragma unroll
    for (int f = 0; f < NF; f++) node[f] = sb2n[f];
    #pragma unroll
    for (int k = 0; k < NF; k++) {
        float s = e1[k];
        #pragma unroll
        for (int f = 0; f < NF; f++)
            node[f] = fmaf(s, sW2n[k * NF + f], node[f]);
    }

    // --- contribution: mask*cut * gate ⊙ node ---
    #pragma unroll
    for (int f = 0; f < NF; f++)
        sred[a * 33 + f] = gm * gate[f] * node[f];

    __syncthreads();

    // reduce over a (warp 0), write coalesced output
    if (a < NF) {
        float s = 0.0f;
        #pragma unroll
        for (int aa = 0; aa < NA; aa++) s += sred[aa * 33 + a];
        out[(size_t)bp * NF + a] = s;
    }
}

// ---------------------------------------------------------------------------
// Launch
// ---------------------------------------------------------------------------
extern "C" void kernel_launch(void* const* d_in, const int* in_sizes, int n_in,
                              void* d_out, int out_size)
{
    const float* scalar    = (const float*)d_in[0];
    const float* srecv     = (const float*)d_in[1];
    const float* expansion = (const float*)d_in[2];
    const float* mask      = (const float*)d_in[3];
    const float* edge      = (const float*)d_in[4];
    const float* W1e       = (const float*)d_in[5];
    const float* b1e       = (const float*)d_in[6];
    const float* W2e       = (const float*)d_in[7];
    const float* b2e       = (const float*)d_in[8];
    const float* W1n       = (const float*)d_in[9];
    const float* b1n       = (const float*)d_in[10];
    const float* W2n       = (const float*)d_in[11];
    const float* b2n       = (const float*)d_in[12];
    float* out = (float*)d_out;

    // Precompute src/tgt linear terms: one warp per row
    int rows    = NB * NP + NB * NA;               // 8384
    int threads = 256;
    int blocks  = (rows * 32 + threads - 1) / threads;
    precompute_kernel<<<blocks, threads>>>(scalar, srecv, W1n, b1n);

    // Main fused kernel: one block per (b,p)
    main_kernel<<<NB * NP, 96>>>(expansion, mask, edge,
                                 W1e, b1e, W2e, b2e, W2n, b2n, out);
}

// round 2
// speedup vs baseline: 1.1282x; 1.1282x over previous
#include <cuda_runtime.h>
#include <cstddef>

// Problem constants (fixed by the dataset)
#define NB 2
#define NP 4096
#define NA 96
#define NF 32
#define NE 20

// Scratch for precomputed linear terms (graph-capturable: static device arrays)
__device__ float g_tgt[NB * NP * NF];   // scalar_reciever @ Wt + b1n
__device__ float g_src[NB * NA * NF];   // scalar @ Ws

// shifted softplus: log(1+e^x) - log(2), numerically stable
__device__ __forceinline__ float sspf(float x) {
    float t = __logf(1.0f + __expf(-fabsf(x)));
    return fmaxf(x, 0.0f) + t - 0.69314718055994531f;
}

// ---- packed f32x2 helpers (Blackwell FFMA2) --------------------------------
__device__ __forceinline__ void fma2(unsigned long long& acc,
                                     unsigned long long s2,
                                     unsigned long long w2) {
    asm("fma.rn.f32x2 %0, %1, %2, %0;" : "+l"(acc) : "l"(s2), "l"(w2));
}
__device__ __forceinline__ unsigned long long pack2(float s) {
    unsigned long long r;
    asm("mov.b64 %0, {%1, %1};" : "=l"(r) : "f"(s));
    return r;
}
__device__ __forceinline__ float2 unpk2(unsigned long long v) {
    float2 r;
    asm("mov.b64 {%0, %1}, %2;" : "=f"(r.x), "=f"(r.y) : "l"(v));
    return r;
}

// ---------------------------------------------------------------------------
// Precompute kernel: one warp per output row, lane = f.
// ---------------------------------------------------------------------------
__global__ void precompute_kernel(const float* __restrict__ scalar,
                                  const float* __restrict__ srecv,
                                  const float* __restrict__ W1n,
                                  const float* __restrict__ b1n)
{
    int gw   = (blockIdx.x * blockDim.x + threadIdx.x) >> 5;
    int lane = threadIdx.x & 31;

    if (gw < NB * NP) {
        float xv  = srecv[gw * NF + lane];
        float acc = b1n[lane];
        #pragma unroll
        for (int k = 0; k < NF; k++) {
            float xk = __shfl_sync(0xffffffffu, xv, k);
            acc = fmaf(xk, W1n[(NF + k) * NF + lane], acc);
        }
        g_tgt[gw * NF + lane] = acc;
    } else if (gw < NB * NP + NB * NA) {
        int r = gw - NB * NP;
        float xv  = scalar[r * NF + lane];
        float acc = 0.0f;
        #pragma unroll
        for (int k = 0; k < NF; k++) {
            float xk = __shfl_sync(0xffffffffu, xv, k);
            acc = fmaf(xk, W1n[k * NF + lane], acc);
        }
        g_src[r * NF + lane] = acc;
    }
}

// ---------------------------------------------------------------------------
// Main kernel: block = one (b,p), thread = one a (96 threads).
// Packed f32x2 FMAs; weights via explicit 128-bit shared loads.
// ---------------------------------------------------------------------------
__global__ __launch_bounds__(96) void main_kernel(
    const float* __restrict__ expansion,   // (B,P,A,E)
    const float* __restrict__ mask,        // (B,P,A,1)
    const float* __restrict__ edge,        // (B,P,A,1)
    const float* __restrict__ W1e,         // (E,F)
    const float* __restrict__ b1e,         // (F)
    const float* __restrict__ W2e,         // (F,F)
    const float* __restrict__ b2e,         // (F)
    const float* __restrict__ W2n,         // (F,F)
    const float* __restrict__ b2n,         // (F)
    float* __restrict__ out)               // (B,P,1,F)
{
    __shared__ __align__(16) float sW1e[NE * NF];
    __shared__ __align__(16) float sW2e[NF * NF];
    __shared__ __align__(16) float sW2n[NF * NF];
    __shared__ __align__(16) float sb2e[NF];
    __shared__ __align__(16) float sb2n[NF];
    __shared__ __align__(16) float sb1e[NF];
    __shared__ __align__(16) float stgt[NF];
    __shared__ float sred[NA * 33];   // padded stride 33: conflict-free

    const int bp = blockIdx.x;       // b*NP + p
    const int a  = threadIdx.x;      // 0..95
    const int b  = bp >> 12;         // NP == 4096

    // Cooperative weight staging
    for (int i = a; i < NE * NF; i += 96) sW1e[i] = W1e[i];
    for (int i = a; i < NF * NF; i += 96) { sW2e[i] = W2e[i]; sW2n[i] = W2n[i]; }
    if (a < NF) {
        sb2e[a] = b2e[a];
        sb2n[a] = b2n[a];
        sb1e[a] = b1e[a];
        stgt[a] = g_tgt[(size_t)bp * NF + a];   // one row per block
    }
    __syncthreads();

    // --- per-thread edge data ---
    float x[NE];
    {
        const float4* xr = reinterpret_cast<const float4*>(
            expansion + ((size_t)bp * NA + a) * NE);   // 80B rows: 16B-aligned
        #pragma unroll
        for (int i = 0; i < NE / 4; i++) {
            float4 v = xr[i];
            x[4 * i + 0] = v.x; x[4 * i + 1] = v.y;
            x[4 * i + 2] = v.z; x[4 * i + 3] = v.w;
        }
    }
    float m = mask[(size_t)bp * NA + a];
    float d = edge[(size_t)bp * NA + a];
    // mask * (1 - sigmoid(5*(d-3.5))) = mask / (1 + exp(5*(d-3.5)))
    float gm = m / (1.0f + __expf(5.0f * (d - 3.5f)));

    // ===== gates path: ssp(x @ W1e + b1e) @ W2e + b2e =====
    unsigned long long acc[NF / 2];
    {
        const unsigned long long* b2 =
            reinterpret_cast<const unsigned long long*>(sb1e);
        #pragma unroll
        for (int j = 0; j < NF / 2; j++) acc[j] = b2[j];
    }
    #pragma unroll
    for (int e = 0; e < NE; e++) {
        unsigned long long s2 = pack2(x[e]);
        const ulonglong2* w4 = reinterpret_cast<const ulonglong2*>(&sW1e[e * NF]);
        #pragma unroll
        for (int j = 0; j < NF / 4; j++) {
            ulonglong2 w = w4[j];
            fma2(acc[2 * j + 0], s2, w.x);
            fma2(acc[2 * j + 1], s2, w.y);
        }
    }
    float e1[NF];
    #pragma unroll
    for (int j = 0; j < NF / 2; j++) {
        float2 v = unpk2(acc[j]);
        e1[2 * j + 0] = sspf(v.x);
        e1[2 * j + 1] = sspf(v.y);
    }

    unsigned long long gate2[NF / 2];
    {
        const unsigned long long* b2 =
            reinterpret_cast<const unsigned long long*>(sb2e);
        #pragma unroll
        for (int j = 0; j < NF / 2; j++) gate2[j] = b2[j];
    }
    #pragma unroll
    for (int k = 0; k < NF; k++) {
        unsigned long long s2 = pack2(e1[k]);
        const ulonglong2* w4 = reinterpret_cast<const ulonglong2*>(&sW2e[k * NF]);
        #pragma unroll
        for (int j = 0; j < NF / 4; j++) {
            ulonglong2 w = w4[j];
            fma2(gate2[2 * j + 0], s2, w.x);
            fma2(gate2[2 * j + 1], s2, w.y);
        }
    }

    // ===== nodes path: ssp(src[a] + tgt[p]) @ W2n + b2n =====
    {
        const float4* srow = reinterpret_cast<const float4*>(
            g_src + ((size_t)b * NA + a) * NF);
        #pragma unroll
        for (int q = 0; q < NF / 4; q++) {
            float4 v = srow[q];
            e1[4 * q + 0] = sspf(v.x + stgt[4 * q + 0]);
            e1[4 * q + 1] = sspf(v.y + stgt[4 * q + 1]);
            e1[4 * q + 2] = sspf(v.z + stgt[4 * q + 2]);
            e1[4 * q + 3] = sspf(v.w + stgt[4 * q + 3]);
        }
    }

    unsigned long long node2[NF / 2];
    {
        const unsigned long long* b2 =
            reinterpret_cast<const unsigned long long*>(sb2n);
        #pragma unroll
        for (int j = 0; j < NF / 2; j++) node2[j] = b2[j];
    }
    #pragma unroll
    for (int k = 0; k < NF; k++) {
        unsigned long long s2 = pack2(e1[k]);
        const ulonglong2* w4 = reinterpret_cast<const ulonglong2*>(&sW2n[k * NF]);
        #pragma unroll
        for (int j = 0; j < NF / 4; j++) {
            ulonglong2 w = w4[j];
            fma2(node2[2 * j + 0], s2, w.x);
            fma2(node2[2 * j + 1], s2, w.y);
        }
    }

    // --- contribution: mask*cut * gate ⊙ node ---
    #pragma unroll
    for (int j = 0; j < NF / 2; j++) {
        float2 g = unpk2(gate2[j]);
        float2 n = unpk2(node2[j]);
        sred[a * 33 + 2 * j + 0] = gm * g.x * n.x;
        sred[a * 33 + 2 * j + 1] = gm * g.y * n.y;
    }

    __syncthreads();

    // reduce over a (warp 0), write coalesced output
    if (a < NF) {
        float s = 0.0f;
        #pragma unroll
        for (int aa = 0; aa < NA; aa++) s += sred[aa * 33 + a];
        out[(size_t)bp * NF + a] = s;
    }
}

// ---------------------------------------------------------------------------
// Launch
// ---------------------------------------------------------------------------
extern "C" void kernel_launch(void* const* d_in, const int* in_sizes, int n_in,
                              void* d_out, int out_size)
{
    const float* scalar    = (const float*)d_in[0];
    const float* srecv     = (const float*)d_in[1];
    const float* expansion = (const float*)d_in[2];
    const float* mask      = (const float*)d_in[3];
    const float* edge      = (const float*)d_in[4];
    const float* W1e       = (const float*)d_in[5];
    const float* b1e       = (const float*)d_in[6];
    const float* W2e       = (const float*)d_in[7];
    const float* b2e       = (const float*)d_in[8];
    const float* W1n       = (const float*)d_in[9];
    const float* b1n       = (const float*)d_in[10];
    const float* W2n       = (const float*)d_in[11];
    const float* b2n       = (const float*)d_in[12];
    float* out = (float*)d_out;

    // Precompute src/tgt linear terms: one warp per row
    int rows    = NB * NP + NB * NA;               // 8384
    int threads = 256;
    int blocks  = (rows * 32 + threads - 1) / threads;
    precompute_kernel<<<blocks, threads>>>(scalar, srecv, W1n, b1n);

    // Main fused kernel: one block per (b,p)
    main_kernel<<<NB * NP, 96>>>(expansion, mask, edge,
                                 W1e, b1e, W2e, b2e, W2n, b2n, out);
}

// round 3
// speedup vs baseline: 1.2578x; 1.1149x over previous
#include <cuda_runtime.h>
#include <cstddef>

// Problem constants (fixed by the dataset)
#define NB 2
#define NP 4096
#define NA 96
#define NF 32
#define NE 20

// Scratch for precomputed linear terms
__device__ float g_tgt[NB * NP * NF];   // scalar_reciever @ Wt + b1n
__device__ float g_src[NB * NA * NF];   // scalar @ Ws

// shifted softplus: log(1+e^x) - log(2), numerically stable
__device__ __forceinline__ float sspf(float x) {
    float t = __logf(1.0f + __expf(-fabsf(x)));
    return fmaxf(x, 0.0f) + t - 0.69314718055994531f;
}

// ---- packed f32x2 helpers (Blackwell FFMA2) --------------------------------
__device__ __forceinline__ void fma2(unsigned long long& acc,
                                     unsigned long long s2,
                                     unsigned long long w2) {
    asm("fma.rn.f32x2 %0, %1, %2, %0;" : "+l"(acc) : "l"(s2), "l"(w2));
}
__device__ __forceinline__ unsigned long long pack2(float s) {
    unsigned long long r;
    asm("mov.b64 %0, {%1, %1};" : "=l"(r) : "f"(s));
    return r;
}
__device__ __forceinline__ float2 unpk2(unsigned long long v) {
    float2 r;
    asm("mov.b64 {%0, %1}, %2;" : "=f"(r.x), "=f"(r.y) : "l"(v));
    return r;
}

// ---------------------------------------------------------------------------
// Precompute kernel: one warp per output row, lane = f.
// ---------------------------------------------------------------------------
__global__ void precompute_kernel(const float* __restrict__ scalar,
                                  const float* __restrict__ srecv,
                                  const float* __restrict__ W1n,
                                  const float* __restrict__ b1n)
{
    int gw   = (blockIdx.x * blockDim.x + threadIdx.x) >> 5;
    int lane = threadIdx.x & 31;

    if (gw < NB * NP) {
        float xv  = srecv[gw * NF + lane];
        float acc = b1n[lane];
        #pragma unroll
        for (int k = 0; k < NF; k++) {
            float xk = __shfl_sync(0xffffffffu, xv, k);
            acc = fmaf(xk, W1n[(NF + k) * NF + lane], acc);
        }
        g_tgt[gw * NF + lane] = acc;
    } else if (gw < NB * NP + NB * NA) {
        int r = gw - NB * NP;
        float xv  = scalar[r * NF + lane];
        float acc = 0.0f;
        #pragma unroll
        for (int k = 0; k < NF; k++) {
            float xk = __shfl_sync(0xffffffffu, xv, k);
            acc = fmaf(xk, W1n[k * NF + lane], acc);
        }
        g_src[r * NF + lane] = acc;
    }
}

// ---------------------------------------------------------------------------
// Main kernel: block = 2 (b,p)'s; thread = 2 edges (a, a+48) of one p.
// Each weight delivered through the smem crossbar feeds 2 items -> half the
// weight wavefront traffic vs 1 item/thread. Packed f32x2 FMAs throughout.
// ---------------------------------------------------------------------------
__global__ __launch_bounds__(96, 4) void main_kernel(
    const float* __restrict__ expansion,   // (B,P,A,E)
    const float* __restrict__ mask,        // (B,P,A,1)
    const float* __restrict__ edge,        // (B,P,A,1)
    const float* __restrict__ W1e,         // (E,F)
    const float* __restrict__ b1e,         // (F)
    const float* __restrict__ W2e,         // (F,F)
    const float* __restrict__ b2e,         // (F)
    const float* __restrict__ W2n,         // (F,F)
    const float* __restrict__ b2n,         // (F)
    float* __restrict__ out)               // (B,P,1,F)
{
    __shared__ __align__(16) float sW1e[NE * NF];
    __shared__ __align__(16) float sW2e[NF * NF];
    __shared__ __align__(16) float sW2n[NF * NF];
    __shared__ __align__(16) float sb1e[NF];
    __shared__ __align__(16) float sb2e[NF];
    __shared__ __align__(16) float sb2n[NF];
    __shared__ __align__(16) float stgt[2][NF];
    // Reused buffer: first as per-thread gate stash (64 f/thread, stride 65),
    // then (after a barrier) as the reduction buffer (32 f/thread, stride 65).
    __shared__ float sbuf[96 * 65];

    const int t   = threadIdx.x;          // 0..95
    const int pl  = t / 48;               // which p within the block
    const int ai  = t - pl * 48;          // 0..47
    const int bp  = 2 * blockIdx.x + pl;  // global b*NP+p
    const int b   = bp >> 12;             // NP == 4096
    const int a0  = ai;                   // first edge
    const int a1  = ai + 48;              // second edge

    // ---- cooperative weight staging ----
    for (int i = t; i < NE * NF; i += 96) sW1e[i] = W1e[i];
    for (int i = t; i < NF * NF; i += 96) { sW2e[i] = W2e[i]; sW2n[i] = W2n[i]; }
    if (t < NF) {
        sb1e[t] = b1e[t]; sb2e[t] = b2e[t]; sb2n[t] = b2n[t];
        stgt[0][t] = g_tgt[(size_t)(2 * blockIdx.x) * NF + t];
        stgt[1][t] = g_tgt[(size_t)(2 * blockIdx.x + 1) * NF + t];
    }
    __syncthreads();

    // ---- per-item edge data ----
    const size_t base0 = (size_t)bp * NA + a0;
    const size_t base1 = (size_t)bp * NA + a1;

    float x0[NE], x1[NE];
    {
        const float4* r0 = reinterpret_cast<const float4*>(expansion + base0 * NE);
        const float4* r1 = reinterpret_cast<const float4*>(expansion + base1 * NE);
        #pragma unroll
        for (int i = 0; i < NE / 4; i++) {
            float4 v0 = r0[i], v1 = r1[i];
            x0[4*i+0] = v0.x; x0[4*i+1] = v0.y; x0[4*i+2] = v0.z; x0[4*i+3] = v0.w;
            x1[4*i+0] = v1.x; x1[4*i+1] = v1.y; x1[4*i+2] = v1.z; x1[4*i+3] = v1.w;
        }
    }
    float gm0, gm1;
    {
        float m0 = mask[base0], m1 = mask[base1];
        float d0 = edge[base0], d1 = edge[base1];
        gm0 = m0 / (1.0f + __expf(5.0f * (d0 - 3.5f)));
        gm1 = m1 / (1.0f + __expf(5.0f * (d1 - 3.5f)));
    }

    // ===== gates layer 1: ssp(x @ W1e + b1e) =====
    unsigned long long acc0[NF / 2], acc1[NF / 2];
    {
        const unsigned long long* bb = reinterpret_cast<const unsigned long long*>(sb1e);
        #pragma unroll
        for (int j = 0; j < NF / 2; j++) { acc0[j] = bb[j]; acc1[j] = bb[j]; }
    }
    #pragma unroll
    for (int e = 0; e < NE; e++) {
        unsigned long long s0 = pack2(x0[e]);
        unsigned long long s1 = pack2(x1[e]);
        const ulonglong2* w4 = reinterpret_cast<const ulonglong2*>(&sW1e[e * NF]);
        #pragma unroll
        for (int j = 0; j < NF / 4; j++) {
            ulonglong2 w = w4[j];
            fma2(acc0[2*j+0], s0, w.x); fma2(acc0[2*j+1], s0, w.y);
            fma2(acc1[2*j+0], s1, w.x); fma2(acc1[2*j+1], s1, w.y);
        }
    }
    float e1g0[NF], e1g1[NF];
    #pragma unroll
    for (int j = 0; j < NF / 2; j++) {
        float2 v0 = unpk2(acc0[j]), v1 = unpk2(acc1[j]);
        e1g0[2*j+0] = sspf(v0.x); e1g0[2*j+1] = sspf(v0.y);
        e1g1[2*j+0] = sspf(v1.x); e1g1[2*j+1] = sspf(v1.y);
    }

    // ===== gates layer 2: @ W2e + b2e =====
    {
        const unsigned long long* bb = reinterpret_cast<const unsigned long long*>(sb2e);
        #pragma unroll
        for (int j = 0; j < NF / 2; j++) { acc0[j] = bb[j]; acc1[j] = bb[j]; }
    }
    #pragma unroll
    for (int k = 0; k < NF; k++) {
        unsigned long long s0 = pack2(e1g0[k]);
        unsigned long long s1 = pack2(e1g1[k]);
        const ulonglong2* w4 = reinterpret_cast<const ulonglong2*>(&sW2e[k * NF]);
        #pragma unroll
        for (int j = 0; j < NF / 4; j++) {
            ulonglong2 w = w4[j];
            fma2(acc0[2*j+0], s0, w.x); fma2(acc0[2*j+1], s0, w.y);
            fma2(acc1[2*j+0], s1, w.x); fma2(acc1[2*j+1], s1, w.y);
        }
    }
    // stash gm * gate to smem (frees 64 registers for the nodes GEMM)
    {
        float* st = &sbuf[t * 65];
        #pragma unroll
        for (int j = 0; j < NF / 2; j++) {
            float2 v0 = unpk2(acc0[j]), v1 = unpk2(acc1[j]);
            st[2*j+0]      = gm0 * v0.x;  st[2*j+1]      = gm0 * v0.y;
            st[NF + 2*j+0] = gm1 * v1.x;  st[NF + 2*j+1] = gm1 * v1.y;
        }
    }

    // ===== nodes path: ssp(src[a] + tgt[p]) @ W2n + b2n =====
    float n1g0[NF], n1g1[NF];
    {
        const float4* s0 = reinterpret_cast<const float4*>(g_src + ((size_t)b * NA + a0) * NF);
        const float4* s1 = reinterpret_cast<const float4*>(g_src + ((size_t)b * NA + a1) * NF);
        #pragma unroll
        for (int q = 0; q < NF / 4; q++) {
            float4 v0 = s0[q], v1 = s1[q];
            float t0 = stgt[pl][4*q+0], t1 = stgt[pl][4*q+1];
            float t2 = stgt[pl][4*q+2], t3 = stgt[pl][4*q+3];
            n1g0[4*q+0] = sspf(v0.x + t0); n1g0[4*q+1] = sspf(v0.y + t1);
            n1g0[4*q+2] = sspf(v0.z + t2); n1g0[4*q+3] = sspf(v0.w + t3);
            n1g1[4*q+0] = sspf(v1.x + t0); n1g1[4*q+1] = sspf(v1.y + t1);
            n1g1[4*q+2] = sspf(v1.z + t2); n1g1[4*q+3] = sspf(v1.w + t3);
        }
    }
    {
        const unsigned long long* bb = reinterpret_cast<const unsigned long long*>(sb2n);
        #pragma unroll
        for (int j = 0; j < NF / 2; j++) { acc0[j] = bb[j]; acc1[j] = bb[j]; }
    }
    #pragma unroll
    for (int k = 0; k < NF; k++) {
        unsigned long long s0 = pack2(n1g0[k]);
        unsigned long long s1 = pack2(n1g1[k]);
        const ulonglong2* w4 = reinterpret_cast<const ulonglong2*>(&sW2n[k * NF]);
        #pragma unroll
        for (int j = 0; j < NF / 4; j++) {
            ulonglong2 w = w4[j];
            fma2(acc0[2*j+0], s0, w.x); fma2(acc0[2*j+1], s0, w.y);
            fma2(acc1[2*j+0], s1, w.x); fma2(acc1[2*j+1], s1, w.y);
        }
    }

    // ---- combine both items in registers: r_f = st0_f*n0_f + st1_f*n1_f ----
    float r[NF];
    {
        const float* st = &sbuf[t * 65];
        #pragma unroll
        for (int j = 0; j < NF / 2; j++) {
            float2 v0 = unpk2(acc0[j]), v1 = unpk2(acc1[j]);
            r[2*j+0] = fmaf(st[2*j+0], v0.x, st[NF + 2*j+0] * v1.x);
            r[2*j+1] = fmaf(st[2*j+1], v0.y, st[NF + 2*j+1] * v1.y);
        }
    }

    __syncthreads();   // everyone done reading their stash; reuse sbuf

    #pragma unroll
    for (int f = 0; f < NF; f++) sbuf[t * 65 + f] = r[f];

    __syncthreads();

    // ---- reduce 48 thread-rows per p, write coalesced output ----
    if (t < NF) {
        float s = 0.0f;
        #pragma unroll
        for (int row = 0; row < 48; row++) s += sbuf[row * 65 + t];
        out[(size_t)(2 * blockIdx.x) * NF + t] = s;
    } else if (t >= 48 && t < 48 + NF) {
        int f = t - 48;
        float s = 0.0f;
        #pragma unroll
        for (int row = 48; row < 96; row++) s += sbuf[row * 65 + f];
        out[(size_t)(2 * blockIdx.x + 1) * NF + f] = s;
    }
}

// ---------------------------------------------------------------------------
// Launch
// ---------------------------------------------------------------------------
extern "C" void kernel_launch(void* const* d_in, const int* in_sizes, int n_in,
                              void* d_out, int out_size)
{
    const float* scalar    = (const float*)d_in[0];
    const float* srecv     = (const float*)d_in[1];
    const float* expansion = (const float*)d_in[2];
    const float* mask      = (const float*)d_in[3];
    const float* edge      = (const float*)d_in[4];
    const float* W1e       = (const float*)d_in[5];
    const float* b1e       = (const float*)d_in[6];
    const float* W2e       = (const float*)d_in[7];
    const float* b2e       = (const float*)d_in[8];
    const float* W1n       = (const float*)d_in[9];
    const float* b1n       = (const float*)d_in[10];
    const float* W2n       = (const float*)d_in[11];
    const float* b2n       = (const float*)d_in[12];
    float* out = (float*)d_out;

    // Precompute src/tgt linear terms: one warp per row
    int rows    = NB * NP + NB * NA;               // 8384
    int threads = 256;
    int blocks  = (rows * 32 + threads - 1) / threads;
    precompute_kernel<<<blocks, threads>>>(scalar, srecv, W1n, b1n);

    // Main fused kernel: one block per 2 (b,p)'s
    main_kernel<<<NB * NP / 2, 96>>>(expansion, mask, edge,
                                     W1e, b1e, W2e, b2e, W2n, b2n, out);
}

// round 4
// speedup vs baseline: 1.3924x; 1.1071x over previous
#include <cuda_runtime.h>
#include <cstddef>

// Problem constants (fixed by the dataset)
#define NB 2
#define NP 4096
#define NA 96
#define NF 32
#define NE 20

// Scratch for precomputed linear terms
__device__ float g_tgt[NB * NP * NF];   // scalar_reciever @ Wt + b1n
__device__ float g_src[NB * NA * NF];   // scalar @ Ws

// Warp-uniform weights live in the constant bank -> LDCU (uniform port),
// completely off the shared-memory crossbar.
__constant__ __align__(16) float cW1e[NE * NF];
__constant__ __align__(16) float cW2e[NF * NF];
__constant__ __align__(16) float cW2n[NF * NF];
__constant__ __align__(16) float cb1e[NF];
__constant__ __align__(16) float cb2e[NF];
__constant__ __align__(16) float cb2n[NF];

// shifted softplus: log(1+e^x) - log(2), numerically stable
__device__ __forceinline__ float sspf(float x) {
    float t = __logf(1.0f + __expf(-fabsf(x)));
    return fmaxf(x, 0.0f) + t - 0.69314718055994531f;
}

// ---- packed f32x2 helpers (Blackwell FFMA2) --------------------------------
__device__ __forceinline__ void fma2(unsigned long long& acc,
                                     unsigned long long s2,
                                     unsigned long long w2) {
    asm("fma.rn.f32x2 %0, %1, %2, %0;" : "+l"(acc) : "l"(s2), "l"(w2));
}
__device__ __forceinline__ unsigned long long pack2(float s) {
    unsigned long long r;
    asm("mov.b64 %0, {%1, %1};" : "=l"(r) : "f"(s));
    return r;
}
__device__ __forceinline__ float2 unpk2(unsigned long long v) {
    float2 r;
    asm("mov.b64 {%0, %1}, %2;" : "=f"(r.x), "=f"(r.y) : "l"(v));
    return r;
}

// ---------------------------------------------------------------------------
// Precompute kernel: one warp per output row, lane = f.
// ---------------------------------------------------------------------------
__global__ void precompute_kernel(const float* __restrict__ scalar,
                                  const float* __restrict__ srecv,
                                  const float* __restrict__ W1n,
                                  const float* __restrict__ b1n)
{
    int gw   = (blockIdx.x * blockDim.x + threadIdx.x) >> 5;
    int lane = threadIdx.x & 31;

    if (gw < NB * NP) {
        float xv  = srecv[gw * NF + lane];
        float acc = b1n[lane];
        #pragma unroll
        for (int k = 0; k < NF; k++) {
            float xk = __shfl_sync(0xffffffffu, xv, k);
            acc = fmaf(xk, W1n[(NF + k) * NF + lane], acc);
        }
        g_tgt[gw * NF + lane] = acc;
    } else if (gw < NB * NP + NB * NA) {
        int r = gw - NB * NP;
        float xv  = scalar[r * NF + lane];
        float acc = 0.0f;
        #pragma unroll
        for (int k = 0; k < NF; k++) {
            float xk = __shfl_sync(0xffffffffu, xv, k);
            acc = fmaf(xk, W1n[k * NF + lane], acc);
        }
        g_src[r * NF + lane] = acc;
    }
}

// ---------------------------------------------------------------------------
// Main kernel: block = one (b,p), thread = one a. Weights from the constant
// bank (uniform port), packed f32x2 FMAs, smem used only for tgt row + the
// final a-reduction.
// ---------------------------------------------------------------------------
__global__ __launch_bounds__(96, 6) void main_kernel(
    const float* __restrict__ expansion,   // (B,P,A,E)
    const float* __restrict__ mask,        // (B,P,A,1)
    const float* __restrict__ edge,        // (B,P,A,1)
    float* __restrict__ out)               // (B,P,1,F)
{
    __shared__ __align__(16) float stgt[NF];
    __shared__ float sred[NA * 33];   // padded stride 33: conflict-free

    const int bp = blockIdx.x;       // b*NP + p
    const int a  = threadIdx.x;      // 0..95
    const int b  = bp >> 12;         // NP == 4096

    if (a < NF) stgt[a] = g_tgt[(size_t)bp * NF + a];
    __syncthreads();

    // --- per-thread edge data ---
    float x[NE];
    {
        const float4* xr = reinterpret_cast<const float4*>(
            expansion + ((size_t)bp * NA + a) * NE);   // 80B rows: 16B-aligned
        #pragma unroll
        for (int i = 0; i < NE / 4; i++) {
            float4 v = xr[i];
            x[4 * i + 0] = v.x; x[4 * i + 1] = v.y;
            x[4 * i + 2] = v.z; x[4 * i + 3] = v.w;
        }
    }
    float m = mask[(size_t)bp * NA + a];
    float d = edge[(size_t)bp * NA + a];
    // mask * (1 - sigmoid(5*(d-3.5))) = mask / (1 + exp(5*(d-3.5)))
    float gm = m / (1.0f + __expf(5.0f * (d - 3.5f)));

    // ===== gates layer 1: ssp(x @ W1e + b1e) =====
    unsigned long long acc[NF / 2];
    {
        const unsigned long long* bb =
            reinterpret_cast<const unsigned long long*>(cb1e);
        #pragma unroll
        for (int j = 0; j < NF / 2; j++) acc[j] = bb[j];
    }
    #pragma unroll
    for (int e = 0; e < NE; e++) {
        unsigned long long s2 = pack2(x[e]);
        const ulonglong2* w4 = reinterpret_cast<const ulonglong2*>(&cW1e[e * NF]);
        #pragma unroll
        for (int j = 0; j < NF / 4; j++) {
            ulonglong2 w = w4[j];
            fma2(acc[2 * j + 0], s2, w.x);
            fma2(acc[2 * j + 1], s2, w.y);
        }
    }
    float e1[NF];
    #pragma unroll
    for (int j = 0; j < NF / 2; j++) {
        float2 v = unpk2(acc[j]);
        e1[2 * j + 0] = sspf(v.x);
        e1[2 * j + 1] = sspf(v.y);
    }

    // ===== gates layer 2: @ W2e + b2e =====
    unsigned long long gate2[NF / 2];
    {
        const unsigned long long* bb =
            reinterpret_cast<const unsigned long long*>(cb2e);
        #pragma unroll
        for (int j = 0; j < NF / 2; j++) gate2[j] = bb[j];
    }
    #pragma unroll
    for (int k = 0; k < NF; k++) {
        unsigned long long s2 = pack2(e1[k]);
        const ulonglong2* w4 = reinterpret_cast<const ulonglong2*>(&cW2e[k * NF]);
        #pragma unroll
        for (int j = 0; j < NF / 4; j++) {
            ulonglong2 w = w4[j];
            fma2(gate2[2 * j + 0], s2, w.x);
            fma2(gate2[2 * j + 1], s2, w.y);
        }
    }

    // ===== nodes path: ssp(src[a] + tgt[p]) @ W2n + b2n =====
    {
        const float4* srow = reinterpret_cast<const float4*>(
            g_src + ((size_t)b * NA + a) * NF);
        #pragma unroll
        for (int q = 0; q < NF / 4; q++) {
            float4 v = srow[q];
            e1[4 * q + 0] = sspf(v.x + stgt[4 * q + 0]);
            e1[4 * q + 1] = sspf(v.y + stgt[4 * q + 1]);
            e1[4 * q + 2] = sspf(v.z + stgt[4 * q + 2]);
            e1[4 * q + 3] = sspf(v.w + stgt[4 * q + 3]);
        }
    }

    {
        const unsigned long long* bb =
            reinterpret_cast<const unsigned long long*>(cb2n);
        #pragma unroll
        for (int j = 0; j < NF / 2; j++) acc[j] = bb[j];
    }
    #pragma unroll
    for (int k = 0; k < NF; k++) {
        unsigned long long s2 = pack2(e1[k]);
        const ulonglong2* w4 = reinterpret_cast<const ulonglong2*>(&cW2n[k * NF]);
        #pragma unroll
        for (int j = 0; j < NF / 4; j++) {
            ulonglong2 w = w4[j];
            fma2(acc[2 * j + 0], s2, w.x);
            fma2(acc[2 * j + 1], s2, w.y);
        }
    }

    // --- contribution: mask*cut * gate ⊙ node ---
    #pragma unroll
    for (int j = 0; j < NF / 2; j++) {
        float2 g = unpk2(gate2[j]);
        float2 n = unpk2(acc[j]);
        sred[a * 33 + 2 * j + 0] = gm * g.x * n.x;
        sred[a * 33 + 2 * j + 1] = gm * g.y * n.y;
    }

    __syncthreads();

    // reduce over a (warp 0), write coalesced output
    if (a < NF) {
        float s = 0.0f;
        #pragma unroll
        for (int aa = 0; aa < NA; aa++) s += sred[aa * 33 + a];
        out[(size_t)bp * NF + a] = s;
    }
}

// ---------------------------------------------------------------------------
// Launch
// ---------------------------------------------------------------------------
extern "C" void kernel_launch(void* const* d_in, const int* in_sizes, int n_in,
                              void* d_out, int out_size)
{
    const float* scalar    = (const float*)d_in[0];
    const float* srecv     = (const float*)d_in[1];
    const float* expansion = (const float*)d_in[2];
    const float* mask      = (const float*)d_in[3];
    const float* edge      = (const float*)d_in[4];
    const float* W1e       = (const float*)d_in[5];
    const float* b1e       = (const float*)d_in[6];
    const float* W2e       = (const float*)d_in[7];
    const float* b2e       = (const float*)d_in[8];
    const float* W1n       = (const float*)d_in[9];
    const float* b1n       = (const float*)d_in[10];
    const float* W2n       = (const float*)d_in[11];
    const float* b2n       = (const float*)d_in[12];
    float* out = (float*)d_out;

    // Stage weights into the constant bank (D2D async copies: graph-capturable)
    cudaMemcpyToSymbolAsync(cW1e, W1e, NE * NF * sizeof(float), 0,
                            cudaMemcpyDeviceToDevice, 0);
    cudaMemcpyToSymbolAsync(cW2e, W2e, NF * NF * sizeof(float), 0,
                            cudaMemcpyDeviceToDevice, 0);
    cudaMemcpyToSymbolAsync(cW2n, W2n, NF * NF * sizeof(float), 0,
                            cudaMemcpyDeviceToDevice, 0);
    cudaMemcpyToSymbolAsync(cb1e, b1e, NF * sizeof(float), 0,
                            cudaMemcpyDeviceToDevice, 0);
    cudaMemcpyToSymbolAsync(cb2e, b2e, NF * sizeof(float), 0,
                            cudaMemcpyDeviceToDevice, 0);
    cudaMemcpyToSymbolAsync(cb2n, b2n, NF * sizeof(float), 0,
                            cudaMemcpyDeviceToDevice, 0);

    // Precompute src/tgt linear terms: one warp per row
    int rows    = NB * NP + NB * NA;               // 8384
    int threads = 256;
    int blocks  = (rows * 32 + threads - 1) / threads;
    precompute_kernel<<<blocks, threads>>>(scalar, srecv, W1n, b1n);

    // Main fused kernel: one block per (b,p)
    main_kernel<<<NB * NP, 96>>>(expansion, mask, edge, out);
}

// round 5
// speedup vs baseline: 1.4627x; 1.0505x over previous
#include <cuda_runtime.h>
#include <cstddef>

// Problem constants (fixed by the dataset)
#define NB 2
#define NP 4096
#define NA 96
#define NF 32
#define NE 20

// Scratch for precomputed linear terms
__device__ float g_tgt[NB * NP * NF];   // scalar_reciever @ Wt + b1n
__device__ float g_src[NB * NA * NF];   // scalar @ Ws

// Gates weights on the constant port (off both smem crossbar and L1)
__constant__ __align__(16) float cW1e[NE * NF];
__constant__ __align__(16) float cW2e[NF * NF];
__constant__ __align__(16) float cb1e[NF];
__constant__ __align__(16) float cb2e[NF];

// shifted softplus: log(1+e^x) - log(2), numerically stable
__device__ __forceinline__ float sspf(float x) {
    float t = __logf(1.0f + __expf(-fabsf(x)));
    return fmaxf(x, 0.0f) + t - 0.69314718055994531f;
}

// ---- packed f32x2 helpers (Blackwell FFMA2) --------------------------------
__device__ __forceinline__ void fma2(unsigned long long& acc,
                                     unsigned long long s2,
                                     unsigned long long w2) {
    asm("fma.rn.f32x2 %0, %1, %2, %0;" : "+l"(acc) : "l"(s2), "l"(w2));
}
__device__ __forceinline__ unsigned long long pack2(float s) {
    unsigned long long r;
    asm("mov.b64 %0, {%1, %1};" : "=l"(r) : "f"(s));
    return r;
}
__device__ __forceinline__ float2 unpk2(unsigned long long v) {
    float2 r;
    asm("mov.b64 {%0, %1}, %2;" : "=f"(r.x), "=f"(r.y) : "l"(v));
    return r;
}

// ---------------------------------------------------------------------------
// Precompute kernel: one warp per output row, lane = f.
// ---------------------------------------------------------------------------
__global__ void precompute_kernel(const float* __restrict__ scalar,
                                  const float* __restrict__ srecv,
                                  const float* __restrict__ W1n,
                                  const float* __restrict__ b1n)
{
    int gw   = (blockIdx.x * blockDim.x + threadIdx.x) >> 5;
    int lane = threadIdx.x & 31;

    if (gw < NB * NP) {
        float xv  = srecv[gw * NF + lane];
        float acc = b1n[lane];
        #pragma unroll
        for (int k = 0; k < NF; k++) {
            float xk = __shfl_sync(0xffffffffu, xv, k);
            acc = fmaf(xk, W1n[(NF + k) * NF + lane], acc);
        }
        g_tgt[gw * NF + lane] = acc;
    } else if (gw < NB * NP + NB * NA) {
        int r = gw - NB * NP;
        float xv  = scalar[r * NF + lane];
        float acc = 0.0f;
        #pragma unroll
        for (int k = 0; k < NF; k++) {
            float xk = __shfl_sync(0xffffffffu, xv, k);
            acc = fmaf(xk, W1n[k * NF + lane], acc);
        }
        g_src[r * NF + lane] = acc;
    }
}

// ---------------------------------------------------------------------------
// Main kernel: block = 2 (b,p)'s; thread = 2 edges (a, a+48) of one p.
// Two independent dependency chains per thread (ILP latency hiding).
// Gates weights via constant port; nodes weights via smem crossbar.
// ---------------------------------------------------------------------------
__global__ __launch_bounds__(96, 4) void main_kernel(
    const float* __restrict__ expansion,   // (B,P,A,E)
    const float* __restrict__ mask,        // (B,P,A,1)
    const float* __restrict__ edge,        // (B,P,A,1)
    const float* __restrict__ W2n,         // (F,F)
    const float* __restrict__ b2n,         // (F)
    float* __restrict__ out)               // (B,P,1,F)
{
    __shared__ __align__(16) float sW2n[NF * NF];
    __shared__ __align__(16) float sb2n[NF];
    __shared__ __align__(16) float stgt[2][NF];
    // Reused: gate stash (64 f/thread, stride 65) then reduction buffer.
    __shared__ float sbuf[96 * 65];

    const int t   = threadIdx.x;          // 0..95
    const int pl  = t / 48;               // which p within the block
    const int ai  = t - pl * 48;          // 0..47
    const int bp  = 2 * blockIdx.x + pl;  // global b*NP+p
    const int b   = bp >> 12;             // NP == 4096
    const int a0  = ai;                   // first edge
    const int a1  = ai + 48;              // second edge

    // ---- cooperative staging ----
    for (int i = t; i < NF * NF; i += 96) sW2n[i] = W2n[i];
    if (t < NF) {
        sb2n[t] = b2n[t];
        stgt[0][t] = g_tgt[(size_t)(2 * blockIdx.x) * NF + t];
        stgt[1][t] = g_tgt[(size_t)(2 * blockIdx.x + 1) * NF + t];
    }
    __syncthreads();

    // ---- per-item edge data ----
    const size_t base0 = (size_t)bp * NA + a0;
    const size_t base1 = (size_t)bp * NA + a1;

    float x0[NE], x1[NE];
    {
        const float4* r0 = reinterpret_cast<const float4*>(expansion + base0 * NE);
        const float4* r1 = reinterpret_cast<const float4*>(expansion + base1 * NE);
        #pragma unroll
        for (int i = 0; i < NE / 4; i++) {
            float4 v0 = r0[i], v1 = r1[i];
            x0[4*i+0] = v0.x; x0[4*i+1] = v0.y; x0[4*i+2] = v0.z; x0[4*i+3] = v0.w;
            x1[4*i+0] = v1.x; x1[4*i+1] = v1.y; x1[4*i+2] = v1.z; x1[4*i+3] = v1.w;
        }
    }
    float gm0, gm1;
    {
        float m0 = mask[base0], m1 = mask[base1];
        float d0 = edge[base0], d1 = edge[base1];
        gm0 = m0 / (1.0f + __expf(5.0f * (d0 - 3.5f)));
        gm1 = m1 / (1.0f + __expf(5.0f * (d1 - 3.5f)));
    }

    // ===== gates layer 1: ssp(x @ W1e + b1e)  [weights: constant port] =====
    unsigned long long acc0[NF / 2], acc1[NF / 2];
    {
        const unsigned long long* bb = reinterpret_cast<const unsigned long long*>(cb1e);
        #pragma unroll
        for (int j = 0; j < NF / 2; j++) { acc0[j] = bb[j]; acc1[j] = bb[j]; }
    }
    #pragma unroll
    for (int e = 0; e < NE; e++) {
        unsigned long long s0 = pack2(x0[e]);
        unsigned long long s1 = pack2(x1[e]);
        const ulonglong2* w4 = reinterpret_cast<const ulonglong2*>(&cW1e[e * NF]);
        #pragma unroll
        for (int j = 0; j < NF / 4; j++) {
            ulonglong2 w = w4[j];
            fma2(acc0[2*j+0], s0, w.x); fma2(acc1[2*j+0], s1, w.x);
            fma2(acc0[2*j+1], s0, w.y); fma2(acc1[2*j+1], s1, w.y);
        }
    }
    float e1g0[NF], e1g1[NF];
    #pragma unroll
    for (int j = 0; j < NF / 2; j++) {
        float2 v0 = unpk2(acc0[j]), v1 = unpk2(acc1[j]);
        e1g0[2*j+0] = sspf(v0.x); e1g0[2*j+1] = sspf(v0.y);
        e1g1[2*j+0] = sspf(v1.x); e1g1[2*j+1] = sspf(v1.y);
    }

    // ===== gates layer 2: @ W2e + b2e  [weights: constant port] =====
    {
        const unsigned long long* bb = reinterpret_cast<const unsigned long long*>(cb2e);
        #pragma unroll
        for (int j = 0; j < NF / 2; j++) { acc0[j] = bb[j]; acc1[j] = bb[j]; }
    }
    #pragma unroll
    for (int k = 0; k < NF; k++) {
        unsigned long long s0 = pack2(e1g0[k]);
        unsigned long long s1 = pack2(e1g1[k]);
        const ulonglong2* w4 = reinterpret_cast<const ulonglong2*>(&cW2e[k * NF]);
        #pragma unroll
        for (int j = 0; j < NF / 4; j++) {
            ulonglong2 w = w4[j];
            fma2(acc0[2*j+0], s0, w.x); fma2(acc1[2*j+0], s1, w.x);
            fma2(acc0[2*j+1], s0, w.y); fma2(acc1[2*j+1], s1, w.y);
        }
    }
    // stash gm * gate to smem (frees 64 registers for the nodes GEMM)
    {
        float* st = &sbuf[t * 65];
        #pragma unroll
        for (int j = 0; j < NF / 2; j++) {
            float2 v0 = unpk2(acc0[j]), v1 = unpk2(acc1[j]);
            st[2*j+0]      = gm0 * v0.x;  st[2*j+1]      = gm0 * v0.y;
            st[NF + 2*j+0] = gm1 * v1.x;  st[NF + 2*j+1] = gm1 * v1.y;
        }
    }

    // ===== nodes path: ssp(src[a] + tgt[p]) @ W2n + b2n  [weights: smem] ====
    float n1g0[NF], n1g1[NF];
    {
        const float4* s0 = reinterpret_cast<const float4*>(g_src + ((size_t)b * NA + a0) * NF);
        const float4* s1 = reinterpret_cast<const float4*>(g_src + ((size_t)b * NA + a1) * NF);
        #pragma unroll
        for (int q = 0; q < NF / 4; q++) {
            float4 v0 = s0[q], v1 = s1[q];
            float t0 = stgt[pl][4*q+0], t1 = stgt[pl][4*q+1];
            float t2 = stgt[pl][4*q+2], t3 = stgt[pl][4*q+3];
            n1g0[4*q+0] = sspf(v0.x + t0); n1g0[4*q+1] = sspf(v0.y + t1);
            n1g0[4*q+2] = sspf(v0.z + t2); n1g0[4*q+3] = sspf(v0.w + t3);
            n1g1[4*q+0] = sspf(v1.x + t0); n1g1[4*q+1] = sspf(v1.y + t1);
            n1g1[4*q+2] = sspf(v1.z + t2); n1g1[4*q+3] = sspf(v1.w + t3);
        }
    }
    {
        const unsigned long long* bb = reinterpret_cast<const unsigned long long*>(sb2n);
        #pragma unroll
        for (int j = 0; j < NF / 2; j++) { acc0[j] = bb[j]; acc1[j] = bb[j]; }
    }
    #pragma unroll
    for (int k = 0; k < NF; k++) {
        unsigned long long s0 = pack2(n1g0[k]);
        unsigned long long s1 = pack2(n1g1[k]);
        const ulonglong2* w4 = reinterpret_cast<const ulonglong2*>(&sW2n[k * NF]);
        #pragma unroll
        for (int j = 0; j < NF / 4; j++) {
            ulonglong2 w = w4[j];
            fma2(acc0[2*j+0], s0, w.x); fma2(acc1[2*j+0], s1, w.x);
            fma2(acc0[2*j+1], s0, w.y); fma2(acc1[2*j+1], s1, w.y);
        }
    }

    // ---- combine both items in registers: r_f = st0_f*n0_f + st1_f*n1_f ----
    float r[NF];
    {
        const float* st = &sbuf[t * 65];
        #pragma unroll
        for (int j = 0; j < NF / 2; j++) {
            float2 v0 = unpk2(acc0[j]), v1 = unpk2(acc1[j]);
            r[2*j+0] = fmaf(st[2*j+0], v0.x, st[NF + 2*j+0] * v1.x);
            r[2*j+1] = fmaf(st[2*j+1], v0.y, st[NF + 2*j+1] * v1.y);
        }
    }

    __syncthreads();   // stash fully consumed; reuse sbuf for reduction

    #pragma unroll
    for (int f = 0; f < NF; f++) sbuf[t * 65 + f] = r[f];

    __syncthreads();

    // ---- reduce 48 thread-rows per p, write coalesced output ----
    if (t < NF) {
        float s = 0.0f;
        #pragma unroll
        for (int row = 0; row < 48; row++) s += sbuf[row * 65 + t];
        out[(size_t)(2 * blockIdx.x) * NF + t] = s;
    } else if (t >= 48 && t < 48 + NF) {
        int f = t - 48;
        float s = 0.0f;
        #pragma unroll
        for (int row = 48; row < 96; row++) s += sbuf[row * 65 + f];
        out[(size_t)(2 * blockIdx.x + 1) * NF + f] = s;
    }
}

// ---------------------------------------------------------------------------
// Launch
// ---------------------------------------------------------------------------
extern "C" void kernel_launch(void* const* d_in, const int* in_sizes, int n_in,
                              void* d_out, int out_size)
{
    const float* scalar    = (const float*)d_in[0];
    const float* srecv     = (const float*)d_in[1];
    const float* expansion = (const float*)d_in[2];
    const float* mask      = (const float*)d_in[3];
    const float* edge      = (const float*)d_in[4];
    const float* W1e       = (const float*)d_in[5];
    const float* b1e       = (const float*)d_in[6];
    const float* W2e       = (const float*)d_in[7];
    const float* b2e       = (const float*)d_in[8];
    const float* W1n       = (const float*)d_in[9];
    const float* b1n       = (const float*)d_in[10];
    const float* W2n       = (const float*)d_in[11];
    const float* b2n       = (const float*)d_in[12];
    float* out = (float*)d_out;

    // Stage gates weights into the constant bank (D2D async: graph-capturable)
    cudaMemcpyToSymbolAsync(cW1e, W1e, NE * NF * sizeof(float), 0,
                            cudaMemcpyDeviceToDevice, 0);
    cudaMemcpyToSymbolAsync(cW2e, W2e, NF * NF * sizeof(float), 0,
                            cudaMemcpyDeviceToDevice, 0);
    cudaMemcpyToSymbolAsync(cb1e, b1e, NF * sizeof(float), 0,
                            cudaMemcpyDeviceToDevice, 0);
    cudaMemcpyToSymbolAsync(cb2e, b2e, NF * sizeof(float), 0,
                            cudaMemcpyDeviceToDevice, 0);

    // Precompute src/tgt linear terms: one warp per row
    int rows    = NB * NP + NB * NA;               // 8384
    int threads = 256;
    int blocks  = (rows * 32 + threads - 1) / threads;
    precompute_kernel<<<blocks, threads>>>(scalar, srecv, W1n, b1n);

    // Main fused kernel: one block per 2 (b,p)'s
    main_kernel<<<NB * NP / 2, 96>>>(expansion, mask, edge, W2n, b2n, out);
}